// round 12
// baseline (speedup 1.0000x reference)
#include <cuda_runtime.h>
#include <cuda_bf16.h>
#include <cuda_fp16.h>
#include <cstdint>

// ---------------------------------------------------------------------------
// Mamba layer. R12: scan remapped to 4 states/thread (64 ch/block, LDS.128
// B/C, 2-deep shfl, 4x fewer warps -> MIO-bound scan relieved).
// GEMMs = R11 single-fp16 HMMA. Everything else unchanged.
//   B=4, L=1024, D_MODEL=512, D_INNER=1024, D_STATE=16, D_CONV=4
// ---------------------------------------------------------------------------

typedef __half h16;

#define NB      4
#define NL      1024
#define DM      512
#define DI      1024
#define DS      16
#define M_ROWS  (NB*NL)          // 4096
#define NC2     1152             // padded: 1024 delta | 16 B | 16 C | 96 pad
#define TQ      16               // scan tile (timesteps)
#define NCH     8                // scan chunks
#define CHL     (NL/NCH)         // 128 steps per chunk

// fp32 scratch
__device__ float g_xr  [M_ROWS * 2048];
__device__ float g_xc  [M_ROWS * DI];
__device__ float g_gate[M_ROWS * DI];
__device__ float g_dbc [M_ROWS * NC2];
__device__ float g_o   [M_ROWS * DM];
__device__ float g_bc  [NC2];

// chunked-scan state: [chunk][b][i][s] flattened
#define CHST (NB * DI * DS)      // 65536 per chunk
__device__ float g_hl [NCH * CHST];
__device__ float g_ap [NCH * CHST];

// fp16 operand scratch
__device__ h16 g_xh [M_ROWS * DM];       // clip(x)
__device__ h16 g_xch[M_ROWS * DI];       // xc
__device__ h16 g_ygh[M_ROWS * DI];       // yg
__device__ h16 g_w1h[2048 * DM];         // W_in^T  [2048,512]
__device__ h16 g_w3h[NC2 * DI];          // Wcomb^T [1152,1024]
__device__ h16 g_w4h[DM * DI];           // W_out^T [512,1024]

// ---------------------------------------------------------------------------
// helpers
// ---------------------------------------------------------------------------
__device__ __forceinline__ uint32_t s2u(const void* p) {
    uint32_t a;
    asm("{ .reg .u64 t; cvta.to.shared.u64 t, %1; cvt.u32.u64 %0, t; }"
        : "=r"(a) : "l"(p));
    return a;
}

__device__ __forceinline__ void cp16(uint32_t dst, const void* src) {
    asm volatile("cp.async.cg.shared.global [%0], [%1], 16;"
                 :: "r"(dst), "l"(src));
}
__device__ __forceinline__ void cp_commit() {
    asm volatile("cp.async.commit_group;");
}
template<int N> __device__ __forceinline__ void cp_wait() {
    asm volatile("cp.async.wait_group %0;" :: "n"(N));
}

__device__ __forceinline__ void ldmx4(uint32_t* r, uint32_t addr) {
    asm volatile("ldmatrix.sync.aligned.m8n8.x4.shared.b16 {%0,%1,%2,%3}, [%4];"
                 : "=r"(r[0]), "=r"(r[1]), "=r"(r[2]), "=r"(r[3]) : "r"(addr));
}

__device__ __forceinline__ void mma16816h(float* c, const uint32_t* a,
                                          uint32_t b0, uint32_t b1) {
    asm volatile(
        "mma.sync.aligned.m16n8k16.row.col.f32.f16.f16.f32 "
        "{%0,%1,%2,%3}, {%4,%5,%6,%7}, {%8,%9}, {%0,%1,%2,%3};"
        : "+f"(c[0]), "+f"(c[1]), "+f"(c[2]), "+f"(c[3])
        : "r"(a[0]), "r"(a[1]), "r"(a[2]), "r"(a[3]), "r"(b0), "r"(b1));
}

// ---------------------------------------------------------------------------
// fp16 MMA GEMM (128x128 CTA tile): C = A * B^T (+ bias), fp32 accumulate.
//   BK=32, 8 warps (2x4), warp tile 64x32, 2-stage cp.async.
// ---------------------------------------------------------------------------
#define APITCH      40
#define MAT_BYTES   (128 * APITCH * 2)        // 10240
#define STAGE_BYTES (2 * MAT_BYTES)           // 20480
#define GEMM_SMEM   (2 * STAGE_BYTES)         // 40960

__device__ __forceinline__ void load_mat(const h16* __restrict__ g,
                                         int base_row, int K, int k0,
                                         uint32_t dst, int tid) {
    #pragma unroll
    for (int it = 0; it < 2; ++it) {
        int j = tid + it * 256;                 // 0..511
        int r = j >> 2;                         // 0..127
        int c = j & 3;                          // 16B chunk
        cp16(dst + r * 80 + c * 16,
             g + (size_t)(base_row + r) * K + k0 + c * 8);
    }
}

template<bool BIAS>
__global__ __launch_bounds__(256)
void mmagemm_kernel(const h16* __restrict__ A, const h16* __restrict__ B,
                    const float* __restrict__ bias, float* __restrict__ C,
                    int K, int ldc)
{
    extern __shared__ char smem[];
    const uint32_t sb = s2u(smem);
    const int tid  = threadIdx.x;
    const int wid  = tid >> 5;
    const int lane = tid & 31;
    const int row0 = blockIdx.y * 128;
    const int col0 = blockIdx.x * 128;
    const int row_w = (wid & 1) * 64;
    const int col_w = (wid >> 1) * 32;

    float acc[4][4][4] = {};

    const int nchunk = K >> 5;

    load_mat(A, row0, K, 0, sb + 0,         tid);
    load_mat(B, col0, K, 0, sb + MAT_BYTES, tid);
    cp_commit();

    const int lrow = lane & 15;
    const int lhal = (lane >> 4) & 1;

    for (int i = 0; i < nchunk; ++i) {
        const uint32_t st = sb + (uint32_t)(i & 1) * STAGE_BYTES;
        if (i + 1 < nchunk) {
            const uint32_t nt = sb + (uint32_t)((i + 1) & 1) * STAGE_BYTES;
            load_mat(A, row0, K, (i + 1) * 32, nt + 0,         tid);
            load_mat(B, col0, K, (i + 1) * 32, nt + MAT_BYTES, tid);
            cp_commit();
            cp_wait<1>();
        } else {
            cp_wait<0>();
        }
        __syncthreads();

        #pragma unroll
        for (int ks = 0; ks < 2; ++ks) {
            uint32_t ah[4][4], bh[2][4];
            const uint32_t koff = ks * 32 + lhal * 16;
            #pragma unroll
            for (int mb = 0; mb < 4; ++mb) {
                const uint32_t ra = (row_w + mb * 16 + lrow) * 80 + koff;
                ldmx4(ah[mb], st + ra);
            }
            #pragma unroll
            for (int nb2 = 0; nb2 < 2; ++nb2) {
                const uint32_t rb = (col_w + nb2 * 16 + lrow) * 80 + koff;
                ldmx4(bh[nb2], st + MAT_BYTES + rb);
            }
            #pragma unroll
            for (int mb = 0; mb < 4; ++mb) {
                #pragma unroll
                for (int nb2 = 0; nb2 < 2; ++nb2) {
                    #pragma unroll
                    for (int hf = 0; hf < 2; ++hf) {
                        mma16816h(acc[mb][nb2 * 2 + hf], ah[mb],
                                  bh[nb2][hf], bh[nb2][hf + 2]);
                    }
                }
            }
        }
        __syncthreads();
    }

    const int g   = lane >> 2;
    const int tig = lane & 3;
    #pragma unroll
    for (int mb = 0; mb < 4; ++mb) {
        #pragma unroll
        for (int nb = 0; nb < 4; ++nb) {
            const int col = col0 + col_w + nb * 8 + tig * 2;
            const int r0  = row0 + row_w + mb * 16 + g;
            float* c = acc[mb][nb];
            float2 v0 = make_float2(c[0], c[1]);
            float2 v1 = make_float2(c[2], c[3]);
            if (BIAS) {
                const float b0 = bias[col], b1 = bias[col + 1];
                v0.x += b0; v0.y += b1;
                v1.x += b0; v1.y += b1;
            }
            *(float2*)&C[(size_t)r0 * ldc + col]       = v0;
            *(float2*)&C[(size_t)(r0 + 8) * ldc + col] = v1;
        }
    }
}

// ---------------------------------------------------------------------------
// fused prep kernel: one launch, segmented grid; all segments run in parallel.
// ---------------------------------------------------------------------------
#define PREP_BLOCKS (8192 + 1024 + 1024 + 32 + 512 + 384 + 5)

__global__ __launch_bounds__(256)
void prep_kernel(const float* __restrict__ x,
                 const float* __restrict__ W_in,
                 const float* __restrict__ W_dt,
                 const float* __restrict__ W_x,
                 const float* __restrict__ W_out,
                 const float* __restrict__ b_dt)
{
    __shared__ float t[32][33];
    int bid = blockIdx.x;
    const int tid = threadIdx.x;

    if (bid < 8192) {                       // S0: clip(x) -> fp16
        int idx = bid * 256 + tid;
        float v = fminf(fmaxf(x[idx], -10.f), 10.f);
        g_xh[idx] = __float2half_rn(v);
        return;
    }
    bid -= 8192;

    const float* src; h16* dst;
    int N, ldk, ro;
    if (bid < 1024)      { src = W_in;  N = 2048; dst = g_w1h; ldk = 512;  ro = 0; }
    else if (bid < 2048) { bid -= 1024; src = W_dt;  N = 1024; dst = g_w3h; ldk = 1024; ro = 0; }
    else if (bid < 2080) { bid -= 2048; src = W_x;   N = 32;   dst = g_w3h; ldk = 1024; ro = 1024; }
    else if (bid < 2592) { bid -= 2080; src = W_out; N = 512;  dst = g_w4h; ldk = 1024; ro = 0; }
    else if (bid < 2976) {                  // S5: zpad w3 rows [1056,1152)
        int idx = (bid - 2592) * 256 + tid;
        g_w3h[(size_t)1056 * DI + idx] = __float2half_rn(0.f);
        return;
    } else {                                // S6: bias
        int idx = (bid - 2976) * 256 + tid;
        if (idx < NC2) g_bc[idx] = (idx < DI) ? b_dt[idx] : 0.f;
        return;
    }

    const int ntx = N >> 5;
    const int bx  = bid % ntx, by = bid / ntx;
    const int k0  = by * 32, n0 = bx * 32;
    const int tx  = tid & 31, ty = tid >> 5;
    #pragma unroll
    for (int r = ty; r < 32; r += 8)
        t[r][tx] = src[(size_t)(k0 + r) * N + n0 + tx];
    __syncthreads();
    #pragma unroll
    for (int r = ty; r < 32; r += 8) {
        float v = t[tx][r];
        dst[(size_t)(ro + n0 + r) * ldk + k0 + tx] = __float2half_rn(v);
    }
}

// ---------------------------------------------------------------------------
// depthwise causal conv + bias + SiLU -> g_xc (fp32) + g_xch (fp16),
// gate = silu(res) -> g_gate
// ---------------------------------------------------------------------------
__global__ void conv_silu_kernel(const float* __restrict__ conv_w,
                                 const float* __restrict__ conv_b)
{
    int idx = blockIdx.x * 256 + threadIdx.x;
    int i = idx & (DI - 1);
    int m = idx >> 10;
    int l = m & (NL - 1);

    float4 w = ((const float4*)conv_w)[i];
    float acc = conv_b[i];
    if (l >= 3) acc = fmaf(w.x, g_xr[(size_t)(m - 3) * 2048 + i], acc);
    if (l >= 2) acc = fmaf(w.y, g_xr[(size_t)(m - 2) * 2048 + i], acc);
    if (l >= 1) acc = fmaf(w.z, g_xr[(size_t)(m - 1) * 2048 + i], acc);
    acc = fmaf(w.w, g_xr[(size_t)m * 2048 + i], acc);

    float sig = 1.f / (1.f + __expf(-acc));
    float xc = acc * sig;
    g_xc[idx]  = xc;
    g_xch[idx] = __float2half_rn(xc);

    float resv = g_xr[(size_t)m * 2048 + 1024 + i];
    float rsig = 1.f / (1.f + __expf(-resv));
    g_gate[idx] = resv * rsig;
}

// ---------------------------------------------------------------------------
// Chunked selective scan, 4 states/thread.
//   Block = 256 thr = 64 channels x 4 lane-groups; lane-group q owns states
//   4q..4q+3 (contiguous -> LDS.128 on B/C, float4 on state arrays).
//   PASS 0: per-chunk scan from h=0; store (h_local[4], A_prod[4]); last
//           chunk's state unused -> early exit.
//   PASS 1: inline combine of prior chunks -> h_in, re-scan, emit y (fp16).
// Grid = NB * 16 * NCH = 512 blocks per pass (~3.5 blocks/SM, 1 wave).
// ---------------------------------------------------------------------------
template<int PASS>
__global__ __launch_bounds__(256)
void scan_pass_kernel(const float* __restrict__ A_log,
                      const float* __restrict__ D_skip)
{
    __shared__ float u_s [2][TQ][64];
    __shared__ float d_s [2][TQ][64];
    __shared__ float gt_s[2][TQ][64];
    __shared__ float bc_s[2][TQ][32];

    const int chunk = blockIdx.x & (NCH - 1);
    if (PASS == 0 && chunk == NCH - 1) return;      // state never consumed

    const int tid = threadIdx.x;
    const int c   = tid >> 2;                       // channel within block
    const int q   = tid & 3;                        // states 4q..4q+3
    const int b     = blockIdx.x >> 7;              // 16*NCH = 128 blocks/batch
    const int itile = (blockIdx.x >> 3) & 15;
    const int i_base = itile << 6;
    const int i   = i_base + c;
    const int mb  = b * NL + chunk * CHL;

    const float4 al4 = ((const float4*)A_log)[q];
    const float ALs[4] = { al4.x, al4.y, al4.z, al4.w };
    const float Dsk = D_skip[i];

    // cooperative load mapping
    const int row_ud = tid >> 6;                    // 0..3
    const int col_ud = tid & 63;
    const int row_bc = tid >> 5;                    // 0..7
    const int col_bc = tid & 31;

    float ru[4], rd[4], rg[4], rbc[2];

    #define LOAD_TILE(tile) do {                                              \
        _Pragma("unroll")                                                     \
        for (int it = 0; it < 4; ++it) {                                      \
            int m = mb + (tile) * TQ + it * 4 + row_ud;                       \
            ru[it] = g_xc  [(size_t)m * DI  + i_base + col_ud];               \
            rd[it] = g_dbc [(size_t)m * NC2 + i_base + col_ud];               \
            if (PASS == 1)                                                    \
                rg[it] = g_gate[(size_t)m * DI + i_base + col_ud];            \
        }                                                                     \
        _Pragma("unroll")                                                     \
        for (int it = 0; it < 2; ++it) {                                      \
            int m = mb + (tile) * TQ + it * 8 + row_bc;                       \
            rbc[it] = g_dbc[(size_t)m * NC2 + 1024 + col_bc];                 \
        }                                                                     \
    } while (0)

    #define STS_TILE(buf) do {                                                \
        _Pragma("unroll")                                                     \
        for (int it = 0; it < 4; ++it) {                                      \
            u_s [buf][it * 4 + row_ud][col_ud] = ru[it];                      \
            d_s [buf][it * 4 + row_ud][col_ud] = rd[it];                      \
            if (PASS == 1)                                                    \
                gt_s[buf][it * 4 + row_ud][col_ud] = rg[it];                  \
        }                                                                     \
        _Pragma("unroll")                                                     \
        for (int it = 0; it < 2; ++it)                                        \
            bc_s[buf][it * 8 + row_bc][col_bc] = rbc[it];                     \
    } while (0)

    LOAD_TILE(0);
    STS_TILE(0);

    const int sidx4 = b * (DI * DS) + i * DS + 4 * q;   // float4-aligned
    float h[4] = {0.f, 0.f, 0.f, 0.f};
    float ap[4];
    if (PASS == 0) {
        ap[0] = ap[1] = ap[2] = ap[3] = 1.f;
    } else {
        for (int ch = 0; ch < chunk; ++ch) {
            float4 a4 = *(const float4*)&g_ap[ch * CHST + sidx4];
            float4 l4 = *(const float4*)&g_hl[ch * CHST + sidx4];
            h[0] = fmaf(a4.x, h[0], l4.x);
            h[1] = fmaf(a4.y, h[1], l4.y);
            h[2] = fmaf(a4.z, h[2], l4.z);
            h[3] = fmaf(a4.w, h[3], l4.w);
        }
    }
    __syncthreads();

    const unsigned fm = 0xffffffffu;
    const int NT = CHL / TQ;                        // 8 tiles per chunk

    for (int tile = 0; tile < NT; ++tile) {
        const int cur = tile & 1, nxt = cur ^ 1;
        if (tile + 1 < NT) LOAD_TILE(tile + 1);

        #pragma unroll
        for (int tt = 0; tt < TQ; ++tt) {
            float u = u_s[cur][tt][c];
            float d = d_s[cur][tt][c];
            float4 Bv = *(const float4*)&bc_s[cur][tt][4 * q];
            float du = d * u;

            #pragma unroll
            for (int j = 0; j < 4; ++j) {
                float a  = fminf(fmaxf(d * ALs[j], -5.f), 5.f);
                float dA = __expf(a);
                if (PASS == 0) ap[j] *= dA;
                float w = du * ((const float*)&Bv)[j];
                h[j] = fmaf(dA, h[j], w);
            }

            if (PASS == 1) {
                float4 Cv = *(const float4*)&bc_s[cur][tt][16 + 4 * q];
                float p = h[0] * Cv.x + h[1] * Cv.y + h[2] * Cv.z + h[3] * Cv.w;
                p += __shfl_xor_sync(fm, p, 1);
                p += __shfl_xor_sync(fm, p, 2);
                if (q == 0) {
                    int m = mb + tile * TQ + tt;
                    float gate = gt_s[cur][tt][c];
                    float v = fmaf(u, Dsk, p) * gate;
                    g_ygh[(size_t)m * DI + i] = __float2half_rn(v);
                }
            }
        }

        if (tile + 1 < NT) STS_TILE(nxt);
        __syncthreads();
    }

    if (PASS == 0) {
        *(float4*)&g_hl[chunk * CHST + sidx4] = make_float4(h[0], h[1], h[2], h[3]);
        *(float4*)&g_ap[chunk * CHST + sidx4] = make_float4(ap[0], ap[1], ap[2], ap[3]);
    }
    #undef LOAD_TILE
    #undef STS_TILE
}

// ---------------------------------------------------------------------------
// residual + layernorm.  one warp per row (512 cols).
// ---------------------------------------------------------------------------
__global__ __launch_bounds__(256)
void ln_kernel(const float* __restrict__ x,
               const float* __restrict__ gamma,
               const float* __restrict__ beta,
               float* __restrict__ out)
{
    const int w = threadIdx.x >> 5;
    const int lane = threadIdx.x & 31;
    const int row = blockIdx.x * 8 + w;

    const float4* orow = (const float4*)&g_o[(size_t)row * DM];
    const float4* xrow = (const float4*)&x[(size_t)row * DM];

    float vals[16];
    float sum = 0.f, sq = 0.f;
    #pragma unroll
    for (int j = 0; j < 4; ++j) {
        float4 o = orow[lane + j * 32];
        float4 xv = xrow[lane + j * 32];
        float r0 = o.x + fminf(fmaxf(xv.x, -10.f), 10.f);
        float r1 = o.y + fminf(fmaxf(xv.y, -10.f), 10.f);
        float r2 = o.z + fminf(fmaxf(xv.z, -10.f), 10.f);
        float r3 = o.w + fminf(fmaxf(xv.w, -10.f), 10.f);
        vals[j * 4 + 0] = r0; vals[j * 4 + 1] = r1;
        vals[j * 4 + 2] = r2; vals[j * 4 + 3] = r3;
        sum += r0 + r1 + r2 + r3;
        sq  += r0 * r0 + r1 * r1 + r2 * r2 + r3 * r3;
    }
    #pragma unroll
    for (int off = 16; off >= 1; off >>= 1) {
        sum += __shfl_xor_sync(0xffffffffu, sum, off);
        sq  += __shfl_xor_sync(0xffffffffu, sq,  off);
    }
    const float mean = sum * (1.f / DM);
    const float var  = sq * (1.f / DM) - mean * mean;
    const float rstd = rsqrtf(var + 1e-5f);

    #pragma unroll
    for (int j = 0; j < 4; ++j) {
        float4 gm = ((const float4*)gamma)[lane + j * 32];
        float4 bt = ((const float4*)beta)[lane + j * 32];
        float4 o;
        o.x = fmaf((vals[j*4+0] - mean) * rstd, gm.x, bt.x);
        o.y = fmaf((vals[j*4+1] - mean) * rstd, gm.y, bt.y);
        o.z = fmaf((vals[j*4+2] - mean) * rstd, gm.z, bt.z);
        o.w = fmaf((vals[j*4+3] - mean) * rstd, gm.w, bt.w);
        ((float4*)&out[(size_t)row * DM])[lane + j * 32] = o;
    }
}

// ---------------------------------------------------------------------------
extern "C" void kernel_launch(void* const* d_in, const int* in_sizes, int n_in,
                              void* d_out, int out_size)
{
    const float* x      = (const float*)d_in[0];
    const float* W_in   = (const float*)d_in[1];
    const float* conv_w = (const float*)d_in[2];
    const float* conv_b = (const float*)d_in[3];
    const float* W_x    = (const float*)d_in[4];
    const float* W_dt   = (const float*)d_in[5];
    const float* b_dt   = (const float*)d_in[6];
    const float* A_log  = (const float*)d_in[7];
    const float* D_skip = (const float*)d_in[8];
    const float* W_out  = (const float*)d_in[9];
    const float* gamma  = (const float*)d_in[10];
    const float* beta   = (const float*)d_in[11];
    float* out = (float*)d_out;

    cudaFuncSetAttribute(mmagemm_kernel<false>,
                         cudaFuncAttributeMaxDynamicSharedMemorySize, GEMM_SMEM);
    cudaFuncSetAttribute(mmagemm_kernel<true>,
                         cudaFuncAttributeMaxDynamicSharedMemorySize, GEMM_SMEM);

    void *p_xr, *p_dbc, *p_o, *p_bc;
    void *p_xh, *p_xch, *p_ygh, *p_w1h, *p_w3h, *p_w4h;
    cudaGetSymbolAddress(&p_xr,  g_xr);
    cudaGetSymbolAddress(&p_dbc, g_dbc);
    cudaGetSymbolAddress(&p_o,   g_o);
    cudaGetSymbolAddress(&p_bc,  g_bc);
    cudaGetSymbolAddress(&p_xh,  g_xh);
    cudaGetSymbolAddress(&p_xch, g_xch);
    cudaGetSymbolAddress(&p_ygh, g_ygh);
    cudaGetSymbolAddress(&p_w1h, g_w1h);
    cudaGetSymbolAddress(&p_w3h, g_w3h);
    cudaGetSymbolAddress(&p_w4h, g_w4h);

    // fused operand prep (clip+cvt x, transpose+cvt weights, zpad, bias)
    prep_kernel<<<PREP_BLOCKS, 256>>>(x, W_in, W_dt, W_x, W_out, b_dt);

    // G1: xr = clip(x) @ W_in   [4096 x 2048], K=512
    {
        dim3 grid(2048 / 128, M_ROWS / 128);
        mmagemm_kernel<false><<<grid, 256, GEMM_SMEM>>>(
            (const h16*)p_xh, (const h16*)p_w1h,
            nullptr, (float*)p_xr, DM, 2048);
    }

    // conv + silu -> xc (fp32 + fp16), gate
    conv_silu_kernel<<<(M_ROWS * DI) / 256, 256>>>(conv_w, conv_b);

    // G3: dbc = xc @ Wcomb + bcomb   [4096 x 1152], K=1024
    {
        dim3 grid(NC2 / 128, M_ROWS / 128);
        mmagemm_kernel<true><<<grid, 256, GEMM_SMEM>>>(
            (const h16*)p_xch, (const h16*)p_w3h,
            (const float*)p_bc, (float*)p_dbc, DI, NC2);
    }

    // chunked selective scan (4 states/thread): pass 0, pass 1
    scan_pass_kernel<0><<<NB * 16 * NCH, 256>>>(A_log, D_skip);
    scan_pass_kernel<1><<<NB * 16 * NCH, 256>>>(A_log, D_skip);

    // G4: o = yg @ W_out   [4096 x 512], K=1024
    {
        dim3 grid(DM / 128, M_ROWS / 128);
        mmagemm_kernel<false><<<grid, 256, GEMM_SMEM>>>(
            (const h16*)p_ygh, (const h16*)p_w4h,
            nullptr, (float*)p_o, DI, DM);
    }

    // residual + layernorm -> out
    ln_kernel<<<M_ROWS / 8, 256>>>(x, gamma, beta, out);
}

// round 13
// speedup vs baseline: 1.0998x; 1.0998x over previous
#include <cuda_runtime.h>
#include <cuda_bf16.h>
#include <cuda_fp16.h>
#include <cstdint>

// ---------------------------------------------------------------------------
// Mamba layer. R13: R11 structure (best, 301.2us) + 3-stage fp16 GEMM
// pipeline (20,480 B/stage -> 61,440 B/CTA; regs still the occupancy limit,
// so 2 CTAs/SM retained — the R8 failure mode does not apply at fp16 size).
// Scan reverted to R11 16-thread/channel mapping.
//   B=4, L=1024, D_MODEL=512, D_INNER=1024, D_STATE=16, D_CONV=4
// ---------------------------------------------------------------------------

typedef __half h16;

#define NB      4
#define NL      1024
#define DM      512
#define DI      1024
#define DS      16
#define M_ROWS  (NB*NL)          // 4096
#define NC2     1152             // padded: 1024 delta | 16 B | 16 C | 96 pad
#define TQ      16               // scan tile (timesteps)
#define NCH     8                // scan chunks
#define CHL     (NL/NCH)         // 128 steps per chunk

// fp32 scratch
__device__ float g_xr  [M_ROWS * 2048];
__device__ float g_xc  [M_ROWS * DI];
__device__ float g_gate[M_ROWS * DI];
__device__ float g_dbc [M_ROWS * NC2];
__device__ float g_o   [M_ROWS * DM];
__device__ float g_bc  [NC2];

// chunked-scan state: [chunk][b][i][s] flattened
#define CHST (NB * DI * DS)      // 65536 per chunk
__device__ float g_hl [NCH * CHST];
__device__ float g_ap [NCH * CHST];

// fp16 operand scratch
__device__ h16 g_xh [M_ROWS * DM];       // clip(x)
__device__ h16 g_xch[M_ROWS * DI];       // xc
__device__ h16 g_ygh[M_ROWS * DI];       // yg
__device__ h16 g_w1h[2048 * DM];         // W_in^T  [2048,512]
__device__ h16 g_w3h[NC2 * DI];          // Wcomb^T [1152,1024]
__device__ h16 g_w4h[DM * DI];           // W_out^T [512,1024]

// ---------------------------------------------------------------------------
// helpers
// ---------------------------------------------------------------------------
__device__ __forceinline__ uint32_t s2u(const void* p) {
    uint32_t a;
    asm("{ .reg .u64 t; cvta.to.shared.u64 t, %1; cvt.u32.u64 %0, t; }"
        : "=r"(a) : "l"(p));
    return a;
}

__device__ __forceinline__ void cp16(uint32_t dst, const void* src) {
    asm volatile("cp.async.cg.shared.global [%0], [%1], 16;"
                 :: "r"(dst), "l"(src));
}
__device__ __forceinline__ void cp_commit() {
    asm volatile("cp.async.commit_group;");
}
template<int N> __device__ __forceinline__ void cp_wait() {
    asm volatile("cp.async.wait_group %0;" :: "n"(N));
}

__device__ __forceinline__ void ldmx4(uint32_t* r, uint32_t addr) {
    asm volatile("ldmatrix.sync.aligned.m8n8.x4.shared.b16 {%0,%1,%2,%3}, [%4];"
                 : "=r"(r[0]), "=r"(r[1]), "=r"(r[2]), "=r"(r[3]) : "r"(addr));
}

__device__ __forceinline__ void mma16816h(float* c, const uint32_t* a,
                                          uint32_t b0, uint32_t b1) {
    asm volatile(
        "mma.sync.aligned.m16n8k16.row.col.f32.f16.f16.f32 "
        "{%0,%1,%2,%3}, {%4,%5,%6,%7}, {%8,%9}, {%0,%1,%2,%3};"
        : "+f"(c[0]), "+f"(c[1]), "+f"(c[2]), "+f"(c[3])
        : "r"(a[0]), "r"(a[1]), "r"(a[2]), "r"(a[3]), "r"(b0), "r"(b1));
}

// ---------------------------------------------------------------------------
// fp16 MMA GEMM (128x128 CTA tile): C = A * B^T (+ bias), fp32 accumulate.
//   BK=32, 8 warps (2x4), warp tile 64x32, 3-stage cp.async (fp16 stage is
//   small enough that regs, not smem, bound occupancy at 2 CTAs/SM).
//   Smem rows padded to 40 h16 (80B): conflict-free ldmatrix.
// ---------------------------------------------------------------------------
#define APITCH      40
#define MAT_BYTES   (128 * APITCH * 2)        // 10240
#define STAGE_BYTES (2 * MAT_BYTES)           // 20480
#define NSTAGE      3
#define GEMM_SMEM   (NSTAGE * STAGE_BYTES)    // 61440

__device__ __forceinline__ void load_mat(const h16* __restrict__ g,
                                         int base_row, int K, int k0,
                                         uint32_t dst, int tid) {
    #pragma unroll
    for (int it = 0; it < 2; ++it) {
        int j = tid + it * 256;                 // 0..511
        int r = j >> 2;                         // 0..127
        int c = j & 3;                          // 16B chunk
        cp16(dst + r * 80 + c * 16,
             g + (size_t)(base_row + r) * K + k0 + c * 8);
    }
}

template<bool BIAS>
__global__ __launch_bounds__(256)
void mmagemm_kernel(const h16* __restrict__ A, const h16* __restrict__ B,
                    const float* __restrict__ bias, float* __restrict__ C,
                    int K, int ldc)
{
    extern __shared__ char smem[];
    const uint32_t sb = s2u(smem);
    const int tid  = threadIdx.x;
    const int wid  = tid >> 5;
    const int lane = tid & 31;
    const int row0 = blockIdx.y * 128;
    const int col0 = blockIdx.x * 128;
    const int row_w = (wid & 1) * 64;
    const int col_w = (wid >> 1) * 32;

    float acc[4][4][4] = {};

    const int nchunk = K >> 5;

    // prologue: chunks 0,1 -> stages 0,1
    load_mat(A, row0, K, 0, sb + 0,         tid);
    load_mat(B, col0, K, 0, sb + MAT_BYTES, tid);
    cp_commit();
    load_mat(A, row0, K, 32, sb + STAGE_BYTES + 0,         tid);
    load_mat(B, col0, K, 32, sb + STAGE_BYTES + MAT_BYTES, tid);
    cp_commit();

    const int lrow = lane & 15;
    const int lhal = (lane >> 4) & 1;

    int stage = 0, nstage = 2;
    for (int i = 0; i < nchunk; ++i) {
        if (i + 2 < nchunk) {
            const uint32_t nt = sb + (uint32_t)nstage * STAGE_BYTES;
            load_mat(A, row0, K, (i + 2) * 32, nt + 0,         tid);
            load_mat(B, col0, K, (i + 2) * 32, nt + MAT_BYTES, tid);
            cp_commit();
            cp_wait<2>();
        } else if (i + 1 < nchunk) {
            cp_wait<1>();
        } else {
            cp_wait<0>();
        }
        __syncthreads();

        const uint32_t st = sb + (uint32_t)stage * STAGE_BYTES;
        #pragma unroll
        for (int ks = 0; ks < 2; ++ks) {
            uint32_t ah[4][4], bh[2][4];
            const uint32_t koff = ks * 32 + lhal * 16;
            #pragma unroll
            for (int mb = 0; mb < 4; ++mb) {
                const uint32_t ra = (row_w + mb * 16 + lrow) * 80 + koff;
                ldmx4(ah[mb], st + ra);
            }
            #pragma unroll
            for (int nb2 = 0; nb2 < 2; ++nb2) {
                const uint32_t rb = (col_w + nb2 * 16 + lrow) * 80 + koff;
                ldmx4(bh[nb2], st + MAT_BYTES + rb);
            }
            #pragma unroll
            for (int mb = 0; mb < 4; ++mb) {
                #pragma unroll
                for (int nb2 = 0; nb2 < 2; ++nb2) {
                    #pragma unroll
                    for (int hf = 0; hf < 2; ++hf) {
                        mma16816h(acc[mb][nb2 * 2 + hf], ah[mb],
                                  bh[nb2][hf], bh[nb2][hf + 2]);
                    }
                }
            }
        }
        __syncthreads();
        stage  = (stage  + 1 == NSTAGE) ? 0 : stage  + 1;
        nstage = (nstage + 1 == NSTAGE) ? 0 : nstage + 1;
    }

    const int g   = lane >> 2;
    const int tig = lane & 3;
    #pragma unroll
    for (int mb = 0; mb < 4; ++mb) {
        #pragma unroll
        for (int nb = 0; nb < 4; ++nb) {
            const int col = col0 + col_w + nb * 8 + tig * 2;
            const int r0  = row0 + row_w + mb * 16 + g;
            float* c = acc[mb][nb];
            float2 v0 = make_float2(c[0], c[1]);
            float2 v1 = make_float2(c[2], c[3]);
            if (BIAS) {
                const float b0 = bias[col], b1 = bias[col + 1];
                v0.x += b0; v0.y += b1;
                v1.x += b0; v1.y += b1;
            }
            *(float2*)&C[(size_t)r0 * ldc + col]       = v0;
            *(float2*)&C[(size_t)(r0 + 8) * ldc + col] = v1;
        }
    }
}

// ---------------------------------------------------------------------------
// fused prep kernel: one launch, segmented grid; all segments run in parallel.
// ---------------------------------------------------------------------------
#define PREP_BLOCKS (8192 + 1024 + 1024 + 32 + 512 + 384 + 5)

__global__ __launch_bounds__(256)
void prep_kernel(const float* __restrict__ x,
                 const float* __restrict__ W_in,
                 const float* __restrict__ W_dt,
                 const float* __restrict__ W_x,
                 const float* __restrict__ W_out,
                 const float* __restrict__ b_dt)
{
    __shared__ float t[32][33];
    int bid = blockIdx.x;
    const int tid = threadIdx.x;

    if (bid < 8192) {                       // S0: clip(x) -> fp16
        int idx = bid * 256 + tid;
        float v = fminf(fmaxf(x[idx], -10.f), 10.f);
        g_xh[idx] = __float2half_rn(v);
        return;
    }
    bid -= 8192;

    const float* src; h16* dst;
    int N, ldk, ro;
    if (bid < 1024)      { src = W_in;  N = 2048; dst = g_w1h; ldk = 512;  ro = 0; }
    else if (bid < 2048) { bid -= 1024; src = W_dt;  N = 1024; dst = g_w3h; ldk = 1024; ro = 0; }
    else if (bid < 2080) { bid -= 2048; src = W_x;   N = 32;   dst = g_w3h; ldk = 1024; ro = 1024; }
    else if (bid < 2592) { bid -= 2080; src = W_out; N = 512;  dst = g_w4h; ldk = 1024; ro = 0; }
    else if (bid < 2976) {                  // S5: zpad w3 rows [1056,1152)
        int idx = (bid - 2592) * 256 + tid;
        g_w3h[(size_t)1056 * DI + idx] = __float2half_rn(0.f);
        return;
    } else {                                // S6: bias
        int idx = (bid - 2976) * 256 + tid;
        if (idx < NC2) g_bc[idx] = (idx < DI) ? b_dt[idx] : 0.f;
        return;
    }

    const int ntx = N >> 5;
    const int bx  = bid % ntx, by = bid / ntx;
    const int k0  = by * 32, n0 = bx * 32;
    const int tx  = tid & 31, ty = tid >> 5;
    #pragma unroll
    for (int r = ty; r < 32; r += 8)
        t[r][tx] = src[(size_t)(k0 + r) * N + n0 + tx];
    __syncthreads();
    #pragma unroll
    for (int r = ty; r < 32; r += 8) {
        float v = t[tx][r];
        dst[(size_t)(ro + n0 + r) * ldk + k0 + tx] = __float2half_rn(v);
    }
}

// ---------------------------------------------------------------------------
// depthwise causal conv + bias + SiLU -> g_xc (fp32) + g_xch (fp16),
// gate = silu(res) -> g_gate
// ---------------------------------------------------------------------------
__global__ void conv_silu_kernel(const float* __restrict__ conv_w,
                                 const float* __restrict__ conv_b)
{
    int idx = blockIdx.x * 256 + threadIdx.x;
    int i = idx & (DI - 1);
    int m = idx >> 10;
    int l = m & (NL - 1);

    float4 w = ((const float4*)conv_w)[i];
    float acc = conv_b[i];
    if (l >= 3) acc = fmaf(w.x, g_xr[(size_t)(m - 3) * 2048 + i], acc);
    if (l >= 2) acc = fmaf(w.y, g_xr[(size_t)(m - 2) * 2048 + i], acc);
    if (l >= 1) acc = fmaf(w.z, g_xr[(size_t)(m - 1) * 2048 + i], acc);
    acc = fmaf(w.w, g_xr[(size_t)m * 2048 + i], acc);

    float sig = 1.f / (1.f + __expf(-acc));
    float xc = acc * sig;
    g_xc[idx]  = xc;
    g_xch[idx] = __float2half_rn(xc);

    float resv = g_xr[(size_t)m * 2048 + 1024 + i];
    float rsig = 1.f / (1.f + __expf(-resv));
    g_gate[idx] = resv * rsig;
}

// ---------------------------------------------------------------------------
// Chunked selective scan (R11 mapping: 16 threads/channel, 1 state/thread).
//   PASS 0: per-chunk scan from h=0; store (h_local, A_prod); last chunk's
//           state unused -> early exit.
//   PASS 1: inline combine of prior chunks -> h_in, re-scan, emit y (fp16).
// Grid = 4*64*8 = 2048 blocks.
// ---------------------------------------------------------------------------
template<int PASS>
__global__ __launch_bounds__(256)
void scan_pass_kernel(const float* __restrict__ A_log,
                      const float* __restrict__ D_skip)
{
    __shared__ float u_s [2][TQ][16];
    __shared__ float d_s [2][TQ][16];
    __shared__ float bc_s[2][TQ][32];

    const int chunk = blockIdx.x & (NCH - 1);
    if (PASS == 0 && chunk == NCH - 1) return;      // state never consumed

    const int tid = threadIdx.x;
    const int c   = tid >> 4;
    const int s   = tid & 15;
    const int b     = blockIdx.x >> 9;
    const int itile = (blockIdx.x >> 3) & 63;
    const int i_base = itile << 4;
    const int i   = i_base + c;
    const int mb  = b * NL + chunk * CHL;

    const float ALs = A_log[s];
    const float Dsk = D_skip[i];

    const int lc   = tid & 15;
    const int lt   = tid >> 4;
    const int bt   = tid >> 5;
    const int bcol = tid & 31;

    float ru, rd, rb0, rb1;

    #define LOAD_TILE(tile) do {                                              \
        int m_ud = mb + (tile) * TQ + lt;                                     \
        ru  = g_xc [(size_t)m_ud * DI + i_base + lc];                         \
        rd  = g_dbc[(size_t)m_ud * NC2 + i_base + lc];                        \
        int m_b0 = mb + (tile) * TQ + bt;                                     \
        rb0 = g_dbc[(size_t)m_b0 * NC2 + 1024 + bcol];                        \
        rb1 = g_dbc[(size_t)(m_b0 + 8) * NC2 + 1024 + bcol];                  \
    } while (0)

    #define STS_TILE(buf) do {                                                \
        u_s [buf][lt][lc]     = ru;                                           \
        d_s [buf][lt][lc]     = rd;                                           \
        bc_s[buf][bt][bcol]   = rb0;                                          \
        bc_s[buf][bt+8][bcol] = rb1;                                          \
    } while (0)

    LOAD_TILE(0);
    STS_TILE(0);

    const int sidx0 = b * (DI * DS) + i * DS + s;
    float h = 0.f, ap;
    if (PASS == 0) {
        ap = 1.f;
    } else {
        for (int ch = 0; ch < chunk; ++ch) {
            int o = ch * CHST + sidx0;
            h = fmaf(g_ap[o], h, g_hl[o]);
        }
    }
    __syncthreads();

    const unsigned fm = 0xffffffffu;
    const int NT = CHL / TQ;                        // 8 tiles per chunk

    for (int tile = 0; tile < NT; ++tile) {
        const int cur = tile & 1, nxt = cur ^ 1;
        if (tile + 1 < NT) LOAD_TILE(tile + 1);

        #pragma unroll
        for (int tt = 0; tt < TQ; ++tt) {
            float u  = u_s [cur][tt][c];
            float d  = d_s [cur][tt][c];
            float Bv = bc_s[cur][tt][s];

            float a  = fminf(fmaxf(d * ALs, -5.f), 5.f);
            float dA = __expf(a);
            if (PASS == 0) ap *= dA;
            h = fmaf(dA, h, d * Bv * u);

            if (PASS == 1) {
                float Cv = bc_s[cur][tt][16 + s];
                float p = h * Cv;
                p += __shfl_xor_sync(fm, p, 1);
                p += __shfl_xor_sync(fm, p, 2);
                p += __shfl_xor_sync(fm, p, 4);
                p += __shfl_xor_sync(fm, p, 8);

                if (s == 0) {
                    int m = mb + tile * TQ + tt;
                    float gate = g_gate[(size_t)m * DI + i];
                    float v = fmaf(u, Dsk, p) * gate;
                    g_ygh[(size_t)m * DI + i] = __float2half_rn(v);
                }
            }
        }

        if (tile + 1 < NT) STS_TILE(nxt);
        __syncthreads();
    }

    if (PASS == 0) {
        int o = chunk * CHST + sidx0;
        g_hl[o] = h;
        g_ap[o] = ap;
    }
    #undef LOAD_TILE
    #undef STS_TILE
}

// ---------------------------------------------------------------------------
// residual + layernorm.  one warp per row (512 cols).
// ---------------------------------------------------------------------------
__global__ __launch_bounds__(256)
void ln_kernel(const float* __restrict__ x,
               const float* __restrict__ gamma,
               const float* __restrict__ beta,
               float* __restrict__ out)
{
    const int w = threadIdx.x >> 5;
    const int lane = threadIdx.x & 31;
    const int row = blockIdx.x * 8 + w;

    const float4* orow = (const float4*)&g_o[(size_t)row * DM];
    const float4* xrow = (const float4*)&x[(size_t)row * DM];

    float vals[16];
    float sum = 0.f, sq = 0.f;
    #pragma unroll
    for (int j = 0; j < 4; ++j) {
        float4 o = orow[lane + j * 32];
        float4 xv = xrow[lane + j * 32];
        float r0 = o.x + fminf(fmaxf(xv.x, -10.f), 10.f);
        float r1 = o.y + fminf(fmaxf(xv.y, -10.f), 10.f);
        float r2 = o.z + fminf(fmaxf(xv.z, -10.f), 10.f);
        float r3 = o.w + fminf(fmaxf(xv.w, -10.f), 10.f);
        vals[j * 4 + 0] = r0; vals[j * 4 + 1] = r1;
        vals[j * 4 + 2] = r2; vals[j * 4 + 3] = r3;
        sum += r0 + r1 + r2 + r3;
        sq  += r0 * r0 + r1 * r1 + r2 * r2 + r3 * r3;
    }
    #pragma unroll
    for (int off = 16; off >= 1; off >>= 1) {
        sum += __shfl_xor_sync(0xffffffffu, sum, off);
        sq  += __shfl_xor_sync(0xffffffffu, sq,  off);
    }
    const float mean = sum * (1.f / DM);
    const float var  = sq * (1.f / DM) - mean * mean;
    const float rstd = rsqrtf(var + 1e-5f);

    #pragma unroll
    for (int j = 0; j < 4; ++j) {
        float4 gm = ((const float4*)gamma)[lane + j * 32];
        float4 bt = ((const float4*)beta)[lane + j * 32];
        float4 o;
        o.x = fmaf((vals[j*4+0] - mean) * rstd, gm.x, bt.x);
        o.y = fmaf((vals[j*4+1] - mean) * rstd, gm.y, bt.y);
        o.z = fmaf((vals[j*4+2] - mean) * rstd, gm.z, bt.z);
        o.w = fmaf((vals[j*4+3] - mean) * rstd, gm.w, bt.w);
        ((float4*)&out[(size_t)row * DM])[lane + j * 32] = o;
    }
}

// ---------------------------------------------------------------------------
extern "C" void kernel_launch(void* const* d_in, const int* in_sizes, int n_in,
                              void* d_out, int out_size)
{
    const float* x      = (const float*)d_in[0];
    const float* W_in   = (const float*)d_in[1];
    const float* conv_w = (const float*)d_in[2];
    const float* conv_b = (const float*)d_in[3];
    const float* W_x    = (const float*)d_in[4];
    const float* W_dt   = (const float*)d_in[5];
    const float* b_dt   = (const float*)d_in[6];
    const float* A_log  = (const float*)d_in[7];
    const float* D_skip = (const float*)d_in[8];
    const float* W_out  = (const float*)d_in[9];
    const float* gamma  = (const float*)d_in[10];
    const float* beta   = (const float*)d_in[11];
    float* out = (float*)d_out;

    cudaFuncSetAttribute(mmagemm_kernel<false>,
                         cudaFuncAttributeMaxDynamicSharedMemorySize, GEMM_SMEM);
    cudaFuncSetAttribute(mmagemm_kernel<true>,
                         cudaFuncAttributeMaxDynamicSharedMemorySize, GEMM_SMEM);

    void *p_xr, *p_dbc, *p_o, *p_bc;
    void *p_xh, *p_xch, *p_ygh, *p_w1h, *p_w3h, *p_w4h;
    cudaGetSymbolAddress(&p_xr,  g_xr);
    cudaGetSymbolAddress(&p_dbc, g_dbc);
    cudaGetSymbolAddress(&p_o,   g_o);
    cudaGetSymbolAddress(&p_bc,  g_bc);
    cudaGetSymbolAddress(&p_xh,  g_xh);
    cudaGetSymbolAddress(&p_xch, g_xch);
    cudaGetSymbolAddress(&p_ygh, g_ygh);
    cudaGetSymbolAddress(&p_w1h, g_w1h);
    cudaGetSymbolAddress(&p_w3h, g_w3h);
    cudaGetSymbolAddress(&p_w4h, g_w4h);

    // fused operand prep (clip+cvt x, transpose+cvt weights, zpad, bias)
    prep_kernel<<<PREP_BLOCKS, 256>>>(x, W_in, W_dt, W_x, W_out, b_dt);

    // G1: xr = clip(x) @ W_in   [4096 x 2048], K=512
    {
        dim3 grid(2048 / 128, M_ROWS / 128);
        mmagemm_kernel<false><<<grid, 256, GEMM_SMEM>>>(
            (const h16*)p_xh, (const h16*)p_w1h,
            nullptr, (float*)p_xr, DM, 2048);
    }

    // conv + silu -> xc (fp32 + fp16), gate
    conv_silu_kernel<<<(M_ROWS * DI) / 256, 256>>>(conv_w, conv_b);

    // G3: dbc = xc @ Wcomb + bcomb   [4096 x 1152], K=1024
    {
        dim3 grid(NC2 / 128, M_ROWS / 128);
        mmagemm_kernel<true><<<grid, 256, GEMM_SMEM>>>(
            (const h16*)p_xch, (const h16*)p_w3h,
            (const float*)p_bc, (float*)p_dbc, DI, NC2);
    }

    // chunked selective scan: pass 0 (local, 7/8 chunks), pass 1 (combine + emit)
    scan_pass_kernel<0><<<NB * 64 * NCH, 256>>>(A_log, D_skip);
    scan_pass_kernel<1><<<NB * 64 * NCH, 256>>>(A_log, D_skip);

    // G4: o = yg @ W_out   [4096 x 512], K=1024
    {
        dim3 grid(DM / 128, M_ROWS / 128);
        mmagemm_kernel<false><<<grid, 256, GEMM_SMEM>>>(
            (const h16*)p_ygh, (const h16*)p_w4h,
            nullptr, (float*)p_o, DI, DM);
    }

    // residual + layernorm -> out
    ln_kernel<<<M_ROWS / 8, 256>>>(x, gamma, beta, out);
}

// round 14
// speedup vs baseline: 1.2340x; 1.1220x over previous
#include <cuda_runtime.h>
#include <cuda_bf16.h>
#include <cuda_fp16.h>
#include <cstdint>

// ---------------------------------------------------------------------------
// Mamba layer. R14: exact R11 structure (best, 301.2us) + GEMM BK 32->64
// (half the sync epochs; 32 MMAs per barrier; 2 CTAs/SM unchanged).
//   B=4, L=1024, D_MODEL=512, D_INNER=1024, D_STATE=16, D_CONV=4
// ---------------------------------------------------------------------------

typedef __half h16;

#define NB      4
#define NL      1024
#define DM      512
#define DI      1024
#define DS      16
#define M_ROWS  (NB*NL)          // 4096
#define NC2     1152             // padded: 1024 delta | 16 B | 16 C | 96 pad
#define TQ      16               // scan tile (timesteps)
#define NCH     8                // scan chunks
#define CHL     (NL/NCH)         // 128 steps per chunk

// fp32 scratch
__device__ float g_xr  [M_ROWS * 2048];
__device__ float g_xc  [M_ROWS * DI];
__device__ float g_gate[M_ROWS * DI];
__device__ float g_dbc [M_ROWS * NC2];
__device__ float g_o   [M_ROWS * DM];
__device__ float g_bc  [NC2];

// chunked-scan state: [chunk][b][i][s] flattened
#define CHST (NB * DI * DS)      // 65536 per chunk
__device__ float g_hl [NCH * CHST];
__device__ float g_ap [NCH * CHST];

// fp16 operand scratch
__device__ h16 g_xh [M_ROWS * DM];       // clip(x)
__device__ h16 g_xch[M_ROWS * DI];       // xc
__device__ h16 g_ygh[M_ROWS * DI];       // yg
__device__ h16 g_w1h[2048 * DM];         // W_in^T  [2048,512]
__device__ h16 g_w3h[NC2 * DI];          // Wcomb^T [1152,1024]
__device__ h16 g_w4h[DM * DI];           // W_out^T [512,1024]

// ---------------------------------------------------------------------------
// helpers
// ---------------------------------------------------------------------------
__device__ __forceinline__ uint32_t s2u(const void* p) {
    uint32_t a;
    asm("{ .reg .u64 t; cvta.to.shared.u64 t, %1; cvt.u32.u64 %0, t; }"
        : "=r"(a) : "l"(p));
    return a;
}

__device__ __forceinline__ void cp16(uint32_t dst, const void* src) {
    asm volatile("cp.async.cg.shared.global [%0], [%1], 16;"
                 :: "r"(dst), "l"(src));
}
__device__ __forceinline__ void cp_commit() {
    asm volatile("cp.async.commit_group;");
}
template<int N> __device__ __forceinline__ void cp_wait() {
    asm volatile("cp.async.wait_group %0;" :: "n"(N));
}

__device__ __forceinline__ void ldmx4(uint32_t* r, uint32_t addr) {
    asm volatile("ldmatrix.sync.aligned.m8n8.x4.shared.b16 {%0,%1,%2,%3}, [%4];"
                 : "=r"(r[0]), "=r"(r[1]), "=r"(r[2]), "=r"(r[3]) : "r"(addr));
}

__device__ __forceinline__ void mma16816h(float* c, const uint32_t* a,
                                          uint32_t b0, uint32_t b1) {
    asm volatile(
        "mma.sync.aligned.m16n8k16.row.col.f32.f16.f16.f32 "
        "{%0,%1,%2,%3}, {%4,%5,%6,%7}, {%8,%9}, {%0,%1,%2,%3};"
        : "+f"(c[0]), "+f"(c[1]), "+f"(c[2]), "+f"(c[3])
        : "r"(a[0]), "r"(a[1]), "r"(a[2]), "r"(a[3]), "r"(b0), "r"(b1));
}

// ---------------------------------------------------------------------------
// fp16 MMA GEMM (128x128 CTA tile): C = A * B^T (+ bias), fp32 accumulate.
//   BK=64, 8 warps (2x4), warp tile 64x32, 2-stage cp.async.
//   Row pitch 144 B (72 h16): ldmatrix bank walk 36r mod 32 is distinct over
//   each 8-row phase -> conflict-free. Stage 36,864 B; 73,728 B total; regs
//   still bound occupancy at 2 CTAs/SM.
// ---------------------------------------------------------------------------
#define RPITCH      144                       // bytes per 64-elem row
#define MAT_BYTES   (128 * RPITCH)            // 18432
#define STAGE_BYTES (2 * MAT_BYTES)           // 36864
#define GEMM_SMEM   (2 * STAGE_BYTES)         // 73728

__device__ __forceinline__ void load_mat(const h16* __restrict__ g,
                                         int base_row, int K, int k0,
                                         uint32_t dst, int tid) {
    #pragma unroll
    for (int it = 0; it < 4; ++it) {
        int j = tid + it * 256;                 // 0..1023
        int r = j >> 3;                         // 0..127
        int c = j & 7;                          // 16B chunk (8 per 128B row)
        cp16(dst + r * RPITCH + c * 16,
             g + (size_t)(base_row + r) * K + k0 + c * 8);
    }
}

template<bool BIAS>
__global__ __launch_bounds__(256)
void mmagemm_kernel(const h16* __restrict__ A, const h16* __restrict__ B,
                    const float* __restrict__ bias, float* __restrict__ C,
                    int K, int ldc)
{
    extern __shared__ char smem[];
    const uint32_t sb = s2u(smem);
    const int tid  = threadIdx.x;
    const int wid  = tid >> 5;
    const int lane = tid & 31;
    const int row0 = blockIdx.y * 128;
    const int col0 = blockIdx.x * 128;
    const int row_w = (wid & 1) * 64;
    const int col_w = (wid >> 1) * 32;

    float acc[4][4][4] = {};

    const int nchunk = K >> 6;

    load_mat(A, row0, K, 0, sb + 0,         tid);
    load_mat(B, col0, K, 0, sb + MAT_BYTES, tid);
    cp_commit();

    const int lrow = lane & 15;
    const int lhal = (lane >> 4) & 1;

    for (int i = 0; i < nchunk; ++i) {
        const uint32_t st = sb + (uint32_t)(i & 1) * STAGE_BYTES;
        if (i + 1 < nchunk) {
            const uint32_t nt = sb + (uint32_t)((i + 1) & 1) * STAGE_BYTES;
            load_mat(A, row0, K, (i + 1) * 64, nt + 0,         tid);
            load_mat(B, col0, K, (i + 1) * 64, nt + MAT_BYTES, tid);
            cp_commit();
            cp_wait<1>();
        } else {
            cp_wait<0>();
        }
        __syncthreads();

        #pragma unroll
        for (int ks = 0; ks < 4; ++ks) {
            uint32_t ah[4][4], bh[2][4];
            const uint32_t koff = ks * 32 + lhal * 16;
            #pragma unroll
            for (int mb = 0; mb < 4; ++mb) {
                const uint32_t ra = (row_w + mb * 16 + lrow) * RPITCH + koff;
                ldmx4(ah[mb], st + ra);
            }
            #pragma unroll
            for (int nb2 = 0; nb2 < 2; ++nb2) {
                const uint32_t rb = (col_w + nb2 * 16 + lrow) * RPITCH + koff;
                ldmx4(bh[nb2], st + MAT_BYTES + rb);
            }
            #pragma unroll
            for (int mb = 0; mb < 4; ++mb) {
                #pragma unroll
                for (int nb2 = 0; nb2 < 2; ++nb2) {
                    #pragma unroll
                    for (int hf = 0; hf < 2; ++hf) {
                        mma16816h(acc[mb][nb2 * 2 + hf], ah[mb],
                                  bh[nb2][hf], bh[nb2][hf + 2]);
                    }
                }
            }
        }
        __syncthreads();
    }

    const int g   = lane >> 2;
    const int tig = lane & 3;
    #pragma unroll
    for (int mb = 0; mb < 4; ++mb) {
        #pragma unroll
        for (int nb = 0; nb < 4; ++nb) {
            const int col = col0 + col_w + nb * 8 + tig * 2;
            const int r0  = row0 + row_w + mb * 16 + g;
            float* c = acc[mb][nb];
            float2 v0 = make_float2(c[0], c[1]);
            float2 v1 = make_float2(c[2], c[3]);
            if (BIAS) {
                const float b0 = bias[col], b1 = bias[col + 1];
                v0.x += b0; v0.y += b1;
                v1.x += b0; v1.y += b1;
            }
            *(float2*)&C[(size_t)r0 * ldc + col]       = v0;
            *(float2*)&C[(size_t)(r0 + 8) * ldc + col] = v1;
        }
    }
}

// ---------------------------------------------------------------------------
// fused prep kernel: one launch, segmented grid; all segments run in parallel.
// ---------------------------------------------------------------------------
#define PREP_BLOCKS (8192 + 1024 + 1024 + 32 + 512 + 384 + 5)

__global__ __launch_bounds__(256)
void prep_kernel(const float* __restrict__ x,
                 const float* __restrict__ W_in,
                 const float* __restrict__ W_dt,
                 const float* __restrict__ W_x,
                 const float* __restrict__ W_out,
                 const float* __restrict__ b_dt)
{
    __shared__ float t[32][33];
    int bid = blockIdx.x;
    const int tid = threadIdx.x;

    if (bid < 8192) {                       // S0: clip(x) -> fp16
        int idx = bid * 256 + tid;
        float v = fminf(fmaxf(x[idx], -10.f), 10.f);
        g_xh[idx] = __float2half_rn(v);
        return;
    }
    bid -= 8192;

    const float* src; h16* dst;
    int N, ldk, ro;
    if (bid < 1024)      { src = W_in;  N = 2048; dst = g_w1h; ldk = 512;  ro = 0; }
    else if (bid < 2048) { bid -= 1024; src = W_dt;  N = 1024; dst = g_w3h; ldk = 1024; ro = 0; }
    else if (bid < 2080) { bid -= 2048; src = W_x;   N = 32;   dst = g_w3h; ldk = 1024; ro = 1024; }
    else if (bid < 2592) { bid -= 2080; src = W_out; N = 512;  dst = g_w4h; ldk = 1024; ro = 0; }
    else if (bid < 2976) {                  // S5: zpad w3 rows [1056,1152)
        int idx = (bid - 2592) * 256 + tid;
        g_w3h[(size_t)1056 * DI + idx] = __float2half_rn(0.f);
        return;
    } else {                                // S6: bias
        int idx = (bid - 2976) * 256 + tid;
        if (idx < NC2) g_bc[idx] = (idx < DI) ? b_dt[idx] : 0.f;
        return;
    }

    const int ntx = N >> 5;
    const int bx  = bid % ntx, by = bid / ntx;
    const int k0  = by * 32, n0 = bx * 32;
    const int tx  = tid & 31, ty = tid >> 5;
    #pragma unroll
    for (int r = ty; r < 32; r += 8)
        t[r][tx] = src[(size_t)(k0 + r) * N + n0 + tx];
    __syncthreads();
    #pragma unroll
    for (int r = ty; r < 32; r += 8) {
        float v = t[tx][r];
        dst[(size_t)(ro + n0 + r) * ldk + k0 + tx] = __float2half_rn(v);
    }
}

// ---------------------------------------------------------------------------
// depthwise causal conv + bias + SiLU -> g_xc (fp32) + g_xch (fp16),
// gate = silu(res) -> g_gate
// ---------------------------------------------------------------------------
__global__ void conv_silu_kernel(const float* __restrict__ conv_w,
                                 const float* __restrict__ conv_b)
{
    int idx = blockIdx.x * 256 + threadIdx.x;
    int i = idx & (DI - 1);
    int m = idx >> 10;
    int l = m & (NL - 1);

    float4 w = ((const float4*)conv_w)[i];
    float acc = conv_b[i];
    if (l >= 3) acc = fmaf(w.x, g_xr[(size_t)(m - 3) * 2048 + i], acc);
    if (l >= 2) acc = fmaf(w.y, g_xr[(size_t)(m - 2) * 2048 + i], acc);
    if (l >= 1) acc = fmaf(w.z, g_xr[(size_t)(m - 1) * 2048 + i], acc);
    acc = fmaf(w.w, g_xr[(size_t)m * 2048 + i], acc);

    float sig = 1.f / (1.f + __expf(-acc));
    float xc = acc * sig;
    g_xc[idx]  = xc;
    g_xch[idx] = __float2half_rn(xc);

    float resv = g_xr[(size_t)m * 2048 + 1024 + i];
    float rsig = 1.f / (1.f + __expf(-resv));
    g_gate[idx] = resv * rsig;
}

// ---------------------------------------------------------------------------
// Chunked selective scan (R11 mapping: 16 threads/channel, 1 state/thread).
//   PASS 0: per-chunk scan from h=0; store (h_local, A_prod); last chunk's
//           state unused -> early exit.
//   PASS 1: inline combine of prior chunks -> h_in, re-scan, emit y (fp16).
// Grid = 4*64*8 = 2048 blocks.
// ---------------------------------------------------------------------------
template<int PASS>
__global__ __launch_bounds__(256)
void scan_pass_kernel(const float* __restrict__ A_log,
                      const float* __restrict__ D_skip)
{
    __shared__ float u_s [2][TQ][16];
    __shared__ float d_s [2][TQ][16];
    __shared__ float bc_s[2][TQ][32];

    const int chunk = blockIdx.x & (NCH - 1);
    if (PASS == 0 && chunk == NCH - 1) return;      // state never consumed

    const int tid = threadIdx.x;
    const int c   = tid >> 4;
    const int s   = tid & 15;
    const int b     = blockIdx.x >> 9;
    const int itile = (blockIdx.x >> 3) & 63;
    const int i_base = itile << 4;
    const int i   = i_base + c;
    const int mb  = b * NL + chunk * CHL;

    const float ALs = A_log[s];
    const float Dsk = D_skip[i];

    const int lc   = tid & 15;
    const int lt   = tid >> 4;
    const int bt   = tid >> 5;
    const int bcol = tid & 31;

    float ru, rd, rb0, rb1;

    #define LOAD_TILE(tile) do {                                              \
        int m_ud = mb + (tile) * TQ + lt;                                     \
        ru  = g_xc [(size_t)m_ud * DI + i_base + lc];                         \
        rd  = g_dbc[(size_t)m_ud * NC2 + i_base + lc];                        \
        int m_b0 = mb + (tile) * TQ + bt;                                     \
        rb0 = g_dbc[(size_t)m_b0 * NC2 + 1024 + bcol];                        \
        rb1 = g_dbc[(size_t)(m_b0 + 8) * NC2 + 1024 + bcol];                  \
    } while (0)

    #define STS_TILE(buf) do {                                                \
        u_s [buf][lt][lc]     = ru;                                           \
        d_s [buf][lt][lc]     = rd;                                           \
        bc_s[buf][bt][bcol]   = rb0;                                          \
        bc_s[buf][bt+8][bcol] = rb1;                                          \
    } while (0)

    LOAD_TILE(0);
    STS_TILE(0);

    const int sidx0 = b * (DI * DS) + i * DS + s;
    float h = 0.f, ap;
    if (PASS == 0) {
        ap = 1.f;
    } else {
        for (int ch = 0; ch < chunk; ++ch) {
            int o = ch * CHST + sidx0;
            h = fmaf(g_ap[o], h, g_hl[o]);
        }
    }
    __syncthreads();

    const unsigned fm = 0xffffffffu;
    const int NT = CHL / TQ;                        // 8 tiles per chunk

    for (int tile = 0; tile < NT; ++tile) {
        const int cur = tile & 1, nxt = cur ^ 1;
        if (tile + 1 < NT) LOAD_TILE(tile + 1);

        #pragma unroll
        for (int tt = 0; tt < TQ; ++tt) {
            float u  = u_s [cur][tt][c];
            float d  = d_s [cur][tt][c];
            float Bv = bc_s[cur][tt][s];

            float a  = fminf(fmaxf(d * ALs, -5.f), 5.f);
            float dA = __expf(a);
            if (PASS == 0) ap *= dA;
            h = fmaf(dA, h, d * Bv * u);

            if (PASS == 1) {
                float Cv = bc_s[cur][tt][16 + s];
                float p = h * Cv;
                p += __shfl_xor_sync(fm, p, 1);
                p += __shfl_xor_sync(fm, p, 2);
                p += __shfl_xor_sync(fm, p, 4);
                p += __shfl_xor_sync(fm, p, 8);

                if (s == 0) {
                    int m = mb + tile * TQ + tt;
                    float gate = g_gate[(size_t)m * DI + i];
                    float v = fmaf(u, Dsk, p) * gate;
                    g_ygh[(size_t)m * DI + i] = __float2half_rn(v);
                }
            }
        }

        if (tile + 1 < NT) STS_TILE(nxt);
        __syncthreads();
    }

    if (PASS == 0) {
        int o = chunk * CHST + sidx0;
        g_hl[o] = h;
        g_ap[o] = ap;
    }
    #undef LOAD_TILE
    #undef STS_TILE
}

// ---------------------------------------------------------------------------
// residual + layernorm.  one warp per row (512 cols).
// ---------------------------------------------------------------------------
__global__ __launch_bounds__(256)
void ln_kernel(const float* __restrict__ x,
               const float* __restrict__ gamma,
               const float* __restrict__ beta,
               float* __restrict__ out)
{
    const int w = threadIdx.x >> 5;
    const int lane = threadIdx.x & 31;
    const int row = blockIdx.x * 8 + w;

    const float4* orow = (const float4*)&g_o[(size_t)row * DM];
    const float4* xrow = (const float4*)&x[(size_t)row * DM];

    float vals[16];
    float sum = 0.f, sq = 0.f;
    #pragma unroll
    for (int j = 0; j < 4; ++j) {
        float4 o = orow[lane + j * 32];
        float4 xv = xrow[lane + j * 32];
        float r0 = o.x + fminf(fmaxf(xv.x, -10.f), 10.f);
        float r1 = o.y + fminf(fmaxf(xv.y, -10.f), 10.f);
        float r2 = o.z + fminf(fmaxf(xv.z, -10.f), 10.f);
        float r3 = o.w + fminf(fmaxf(xv.w, -10.f), 10.f);
        vals[j * 4 + 0] = r0; vals[j * 4 + 1] = r1;
        vals[j * 4 + 2] = r2; vals[j * 4 + 3] = r3;
        sum += r0 + r1 + r2 + r3;
        sq  += r0 * r0 + r1 * r1 + r2 * r2 + r3 * r3;
    }
    #pragma unroll
    for (int off = 16; off >= 1; off >>= 1) {
        sum += __shfl_xor_sync(0xffffffffu, sum, off);
        sq  += __shfl_xor_sync(0xffffffffu, sq,  off);
    }
    const float mean = sum * (1.f / DM);
    const float var  = sq * (1.f / DM) - mean * mean;
    const float rstd = rsqrtf(var + 1e-5f);

    #pragma unroll
    for (int j = 0; j < 4; ++j) {
        float4 gm = ((const float4*)gamma)[lane + j * 32];
        float4 bt = ((const float4*)beta)[lane + j * 32];
        float4 o;
        o.x = fmaf((vals[j*4+0] - mean) * rstd, gm.x, bt.x);
        o.y = fmaf((vals[j*4+1] - mean) * rstd, gm.y, bt.y);
        o.z = fmaf((vals[j*4+2] - mean) * rstd, gm.z, bt.z);
        o.w = fmaf((vals[j*4+3] - mean) * rstd, gm.w, bt.w);
        ((float4*)&out[(size_t)row * DM])[lane + j * 32] = o;
    }
}

// ---------------------------------------------------------------------------
extern "C" void kernel_launch(void* const* d_in, const int* in_sizes, int n_in,
                              void* d_out, int out_size)
{
    const float* x      = (const float*)d_in[0];
    const float* W_in   = (const float*)d_in[1];
    const float* conv_w = (const float*)d_in[2];
    const float* conv_b = (const float*)d_in[3];
    const float* W_x    = (const float*)d_in[4];
    const float* W_dt   = (const float*)d_in[5];
    const float* b_dt   = (const float*)d_in[6];
    const float* A_log  = (const float*)d_in[7];
    const float* D_skip = (const float*)d_in[8];
    const float* W_out  = (const float*)d_in[9];
    const float* gamma  = (const float*)d_in[10];
    const float* beta   = (const float*)d_in[11];
    float* out = (float*)d_out;

    cudaFuncSetAttribute(mmagemm_kernel<false>,
                         cudaFuncAttributeMaxDynamicSharedMemorySize, GEMM_SMEM);
    cudaFuncSetAttribute(mmagemm_kernel<true>,
                         cudaFuncAttributeMaxDynamicSharedMemorySize, GEMM_SMEM);

    void *p_xr, *p_dbc, *p_o, *p_bc;
    void *p_xh, *p_xch, *p_ygh, *p_w1h, *p_w3h, *p_w4h;
    cudaGetSymbolAddress(&p_xr,  g_xr);
    cudaGetSymbolAddress(&p_dbc, g_dbc);
    cudaGetSymbolAddress(&p_o,   g_o);
    cudaGetSymbolAddress(&p_bc,  g_bc);
    cudaGetSymbolAddress(&p_xh,  g_xh);
    cudaGetSymbolAddress(&p_xch, g_xch);
    cudaGetSymbolAddress(&p_ygh, g_ygh);
    cudaGetSymbolAddress(&p_w1h, g_w1h);
    cudaGetSymbolAddress(&p_w3h, g_w3h);
    cudaGetSymbolAddress(&p_w4h, g_w4h);

    // fused operand prep (clip+cvt x, transpose+cvt weights, zpad, bias)
    prep_kernel<<<PREP_BLOCKS, 256>>>(x, W_in, W_dt, W_x, W_out, b_dt);

    // G1: xr = clip(x) @ W_in   [4096 x 2048], K=512
    {
        dim3 grid(2048 / 128, M_ROWS / 128);
        mmagemm_kernel<false><<<grid, 256, GEMM_SMEM>>>(
            (const h16*)p_xh, (const h16*)p_w1h,
            nullptr, (float*)p_xr, DM, 2048);
    }

    // conv + silu -> xc (fp32 + fp16), gate
    conv_silu_kernel<<<(M_ROWS * DI) / 256, 256>>>(conv_w, conv_b);

    // G3: dbc = xc @ Wcomb + bcomb   [4096 x 1152], K=1024
    {
        dim3 grid(NC2 / 128, M_ROWS / 128);
        mmagemm_kernel<true><<<grid, 256, GEMM_SMEM>>>(
            (const h16*)p_xch, (const h16*)p_w3h,
            (const float*)p_bc, (float*)p_dbc, DI, NC2);
    }

    // chunked selective scan: pass 0 (local, 7/8 chunks), pass 1 (combine + emit)
    scan_pass_kernel<0><<<NB * 64 * NCH, 256>>>(A_log, D_skip);
    scan_pass_kernel<1><<<NB * 64 * NCH, 256>>>(A_log, D_skip);

    // G4: o = yg @ W_out   [4096 x 512], K=1024
    {
        dim3 grid(DM / 128, M_ROWS / 128);
        mmagemm_kernel<false><<<grid, 256, GEMM_SMEM>>>(
            (const h16*)p_ygh, (const h16*)p_w4h,
            nullptr, (float*)p_o, DI, DM);
    }

    // residual + layernorm -> out
    ln_kernel<<<M_ROWS / 8, 256>>>(x, gamma, beta, out);
}

// round 16
// speedup vs baseline: 1.4657x; 1.1878x over previous
#include <cuda_runtime.h>
#include <cuda_bf16.h>
#include <cuda_fp16.h>
#include <cstdint>

// ---------------------------------------------------------------------------
// Mamba layer. R16 (= R15 with ex2 fixed): R14 base + scan micro-opts:
//   (u,d,gate) packed float4 -> 1 LDS.128; (B,C) interleaved float2 ->
//   1 LDS.64; exp in exp2 domain via ex2.approx (one less FMUL/step).
//   R11/R14 thread mapping preserved (16 thr/channel, 1 state/thread).
//   B=4, L=1024, D_MODEL=512, D_INNER=1024, D_STATE=16, D_CONV=4
// ---------------------------------------------------------------------------

typedef __half h16;

#define NB      4
#define NL      1024
#define DM      512
#define DI      1024
#define DS      16
#define M_ROWS  (NB*NL)          // 4096
#define NC2     1152             // padded: 1024 delta | 16 B | 16 C | 96 pad
#define TQ      16               // scan tile (timesteps)
#define NCH     8                // scan chunks
#define CHL     (NL/NCH)         // 128 steps per chunk
#define LOG2E   1.44269504f
#define CLP2    7.2134752f       // 5 * log2(e)

// fp32 scratch
__device__ float g_xr  [M_ROWS * 2048];
__device__ float g_xc  [M_ROWS * DI];
__device__ float g_gate[M_ROWS * DI];
__device__ float g_dbc [M_ROWS * NC2];
__device__ float g_o   [M_ROWS * DM];
__device__ float g_bc  [NC2];

// chunked-scan state: [chunk][b][i][s] flattened
#define CHST (NB * DI * DS)      // 65536 per chunk
__device__ float g_hl [NCH * CHST];
__device__ float g_ap [NCH * CHST];

// fp16 operand scratch
__device__ h16 g_xh [M_ROWS * DM];       // clip(x)
__device__ h16 g_xch[M_ROWS * DI];       // xc
__device__ h16 g_ygh[M_ROWS * DI];       // yg
__device__ h16 g_w1h[2048 * DM];         // W_in^T  [2048,512]
__device__ h16 g_w3h[NC2 * DI];          // Wcomb^T [1152,1024]
__device__ h16 g_w4h[DM * DI];           // W_out^T [512,1024]

// ---------------------------------------------------------------------------
// helpers
// ---------------------------------------------------------------------------
__device__ __forceinline__ uint32_t s2u(const void* p) {
    uint32_t a;
    asm("{ .reg .u64 t; cvta.to.shared.u64 t, %1; cvt.u32.u64 %0, t; }"
        : "=r"(a) : "l"(p));
    return a;
}

__device__ __forceinline__ float ex2f(float x) {
    float r;
    asm("ex2.approx.f32 %0, %1;" : "=f"(r) : "f"(x));
    return r;
}

__device__ __forceinline__ void cp16(uint32_t dst, const void* src) {
    asm volatile("cp.async.cg.shared.global [%0], [%1], 16;"
                 :: "r"(dst), "l"(src));
}
__device__ __forceinline__ void cp_commit() {
    asm volatile("cp.async.commit_group;");
}
template<int N> __device__ __forceinline__ void cp_wait() {
    asm volatile("cp.async.wait_group %0;" :: "n"(N));
}

__device__ __forceinline__ void ldmx4(uint32_t* r, uint32_t addr) {
    asm volatile("ldmatrix.sync.aligned.m8n8.x4.shared.b16 {%0,%1,%2,%3}, [%4];"
                 : "=r"(r[0]), "=r"(r[1]), "=r"(r[2]), "=r"(r[3]) : "r"(addr));
}

__device__ __forceinline__ void mma16816h(float* c, const uint32_t* a,
                                          uint32_t b0, uint32_t b1) {
    asm volatile(
        "mma.sync.aligned.m16n8k16.row.col.f32.f16.f16.f32 "
        "{%0,%1,%2,%3}, {%4,%5,%6,%7}, {%8,%9}, {%0,%1,%2,%3};"
        : "+f"(c[0]), "+f"(c[1]), "+f"(c[2]), "+f"(c[3])
        : "r"(a[0]), "r"(a[1]), "r"(a[2]), "r"(a[3]), "r"(b0), "r"(b1));
}

// ---------------------------------------------------------------------------
// fp16 MMA GEMM (128x128 CTA tile): C = A * B^T (+ bias), fp32 accumulate.
//   BK=64, 8 warps (2x4), warp tile 64x32, 2-stage cp.async. (R14 config.)
// ---------------------------------------------------------------------------
#define RPITCH      144                       // bytes per 64-elem row
#define MAT_BYTES   (128 * RPITCH)            // 18432
#define STAGE_BYTES (2 * MAT_BYTES)           // 36864
#define GEMM_SMEM   (2 * STAGE_BYTES)         // 73728

__device__ __forceinline__ void load_mat(const h16* __restrict__ g,
                                         int base_row, int K, int k0,
                                         uint32_t dst, int tid) {
    #pragma unroll
    for (int it = 0; it < 4; ++it) {
        int j = tid + it * 256;                 // 0..1023
        int r = j >> 3;                         // 0..127
        int c = j & 7;                          // 16B chunk (8 per 128B row)
        cp16(dst + r * RPITCH + c * 16,
             g + (size_t)(base_row + r) * K + k0 + c * 8);
    }
}

template<bool BIAS>
__global__ __launch_bounds__(256)
void mmagemm_kernel(const h16* __restrict__ A, const h16* __restrict__ B,
                    const float* __restrict__ bias, float* __restrict__ C,
                    int K, int ldc)
{
    extern __shared__ char smem[];
    const uint32_t sb = s2u(smem);
    const int tid  = threadIdx.x;
    const int wid  = tid >> 5;
    const int lane = tid & 31;
    const int row0 = blockIdx.y * 128;
    const int col0 = blockIdx.x * 128;
    const int row_w = (wid & 1) * 64;
    const int col_w = (wid >> 1) * 32;

    float acc[4][4][4] = {};

    const int nchunk = K >> 6;

    load_mat(A, row0, K, 0, sb + 0,         tid);
    load_mat(B, col0, K, 0, sb + MAT_BYTES, tid);
    cp_commit();

    const int lrow = lane & 15;
    const int lhal = (lane >> 4) & 1;

    for (int i = 0; i < nchunk; ++i) {
        const uint32_t st = sb + (uint32_t)(i & 1) * STAGE_BYTES;
        if (i + 1 < nchunk) {
            const uint32_t nt = sb + (uint32_t)((i + 1) & 1) * STAGE_BYTES;
            load_mat(A, row0, K, (i + 1) * 64, nt + 0,         tid);
            load_mat(B, col0, K, (i + 1) * 64, nt + MAT_BYTES, tid);
            cp_commit();
            cp_wait<1>();
        } else {
            cp_wait<0>();
        }
        __syncthreads();

        #pragma unroll
        for (int ks = 0; ks < 4; ++ks) {
            uint32_t ah[4][4], bh[2][4];
            const uint32_t koff = ks * 32 + lhal * 16;
            #pragma unroll
            for (int mb = 0; mb < 4; ++mb) {
                const uint32_t ra = (row_w + mb * 16 + lrow) * RPITCH + koff;
                ldmx4(ah[mb], st + ra);
            }
            #pragma unroll
            for (int nb2 = 0; nb2 < 2; ++nb2) {
                const uint32_t rb = (col_w + nb2 * 16 + lrow) * RPITCH + koff;
                ldmx4(bh[nb2], st + MAT_BYTES + rb);
            }
            #pragma unroll
            for (int mb = 0; mb < 4; ++mb) {
                #pragma unroll
                for (int nb2 = 0; nb2 < 2; ++nb2) {
                    #pragma unroll
                    for (int hf = 0; hf < 2; ++hf) {
                        mma16816h(acc[mb][nb2 * 2 + hf], ah[mb],
                                  bh[nb2][hf], bh[nb2][hf + 2]);
                    }
                }
            }
        }
        __syncthreads();
    }

    const int g   = lane >> 2;
    const int tig = lane & 3;
    #pragma unroll
    for (int mb = 0; mb < 4; ++mb) {
        #pragma unroll
        for (int nb = 0; nb < 4; ++nb) {
            const int col = col0 + col_w + nb * 8 + tig * 2;
            const int r0  = row0 + row_w + mb * 16 + g;
            float* c = acc[mb][nb];
            float2 v0 = make_float2(c[0], c[1]);
            float2 v1 = make_float2(c[2], c[3]);
            if (BIAS) {
                const float b0 = bias[col], b1 = bias[col + 1];
                v0.x += b0; v0.y += b1;
                v1.x += b0; v1.y += b1;
            }
            *(float2*)&C[(size_t)r0 * ldc + col]       = v0;
            *(float2*)&C[(size_t)(r0 + 8) * ldc + col] = v1;
        }
    }
}

// ---------------------------------------------------------------------------
// fused prep kernel: one launch, segmented grid; all segments run in parallel.
// ---------------------------------------------------------------------------
#define PREP_BLOCKS (8192 + 1024 + 1024 + 32 + 512 + 384 + 5)

__global__ __launch_bounds__(256)
void prep_kernel(const float* __restrict__ x,
                 const float* __restrict__ W_in,
                 const float* __restrict__ W_dt,
                 const float* __restrict__ W_x,
                 const float* __restrict__ W_out,
                 const float* __restrict__ b_dt)
{
    __shared__ float t[32][33];
    int bid = blockIdx.x;
    const int tid = threadIdx.x;

    if (bid < 8192) {                       // S0: clip(x) -> fp16
        int idx = bid * 256 + tid;
        float v = fminf(fmaxf(x[idx], -10.f), 10.f);
        g_xh[idx] = __float2half_rn(v);
        return;
    }
    bid -= 8192;

    const float* src; h16* dst;
    int N, ldk, ro;
    if (bid < 1024)      { src = W_in;  N = 2048; dst = g_w1h; ldk = 512;  ro = 0; }
    else if (bid < 2048) { bid -= 1024; src = W_dt;  N = 1024; dst = g_w3h; ldk = 1024; ro = 0; }
    else if (bid < 2080) { bid -= 2048; src = W_x;   N = 32;   dst = g_w3h; ldk = 1024; ro = 1024; }
    else if (bid < 2592) { bid -= 2080; src = W_out; N = 512;  dst = g_w4h; ldk = 1024; ro = 0; }
    else if (bid < 2976) {                  // S5: zpad w3 rows [1056,1152)
        int idx = (bid - 2592) * 256 + tid;
        g_w3h[(size_t)1056 * DI + idx] = __float2half_rn(0.f);
        return;
    } else {                                // S6: bias
        int idx = (bid - 2976) * 256 + tid;
        if (idx < NC2) g_bc[idx] = (idx < DI) ? b_dt[idx] : 0.f;
        return;
    }

    const int ntx = N >> 5;
    const int bx  = bid % ntx, by = bid / ntx;
    const int k0  = by * 32, n0 = bx * 32;
    const int tx  = tid & 31, ty = tid >> 5;
    #pragma unroll
    for (int r = ty; r < 32; r += 8)
        t[r][tx] = src[(size_t)(k0 + r) * N + n0 + tx];
    __syncthreads();
    #pragma unroll
    for (int r = ty; r < 32; r += 8) {
        float v = t[tx][r];
        dst[(size_t)(ro + n0 + r) * ldk + k0 + tx] = __float2half_rn(v);
    }
}

// ---------------------------------------------------------------------------
// depthwise causal conv + bias + SiLU -> g_xc (fp32) + g_xch (fp16),
// gate = silu(res) -> g_gate
// ---------------------------------------------------------------------------
__global__ void conv_silu_kernel(const float* __restrict__ conv_w,
                                 const float* __restrict__ conv_b)
{
    int idx = blockIdx.x * 256 + threadIdx.x;
    int i = idx & (DI - 1);
    int m = idx >> 10;
    int l = m & (NL - 1);

    float4 w = ((const float4*)conv_w)[i];
    float acc = conv_b[i];
    if (l >= 3) acc = fmaf(w.x, g_xr[(size_t)(m - 3) * 2048 + i], acc);
    if (l >= 2) acc = fmaf(w.y, g_xr[(size_t)(m - 2) * 2048 + i], acc);
    if (l >= 1) acc = fmaf(w.z, g_xr[(size_t)(m - 1) * 2048 + i], acc);
    acc = fmaf(w.w, g_xr[(size_t)m * 2048 + i], acc);

    float sig = 1.f / (1.f + __expf(-acc));
    float xc = acc * sig;
    g_xc[idx]  = xc;
    g_xch[idx] = __float2half_rn(xc);

    float resv = g_xr[(size_t)m * 2048 + 1024 + i];
    float rsig = 1.f / (1.f + __expf(-resv));
    g_gate[idx] = resv * rsig;
}

// ---------------------------------------------------------------------------
// Chunked selective scan (R11 mapping: 16 threads/channel, 1 state/thread).
//   ud_s: (u, d, gate, -) float4 -> one LDS.128 per step.
//   bc_s: (B, C) float2        -> one LDS.64 per step.
//   exp in exp2 domain: clamp(d*ALs*log2e, +-5log2e) then ex2.approx.
//   PASS 0: per-chunk scan from h=0; store (h_local, A_prod); last chunk's
//           state unused -> early exit.
//   PASS 1: inline combine of prior chunks -> h_in, re-scan, emit y (fp16).
// Grid = 4*64*8 = 2048 blocks.
// ---------------------------------------------------------------------------
template<int PASS>
__global__ __launch_bounds__(256)
void scan_pass_kernel(const float* __restrict__ A_log,
                      const float* __restrict__ D_skip)
{
    __shared__ float4 ud_s[2][TQ][16];      // (u, d, gate, -)
    __shared__ float2 bc_s[2][TQ][16];      // (B, C)

    const int chunk = blockIdx.x & (NCH - 1);
    if (PASS == 0 && chunk == NCH - 1) return;      // state never consumed

    const int tid = threadIdx.x;
    const int c   = tid >> 4;
    const int s   = tid & 15;
    const int b     = blockIdx.x >> 9;
    const int itile = (blockIdx.x >> 3) & 63;
    const int i_base = itile << 4;
    const int i   = i_base + c;
    const int mb  = b * NL + chunk * CHL;

    const float ALs2 = A_log[s] * LOG2E;
    const float Dsk = D_skip[i];

    // cooperative load mapping: thread (lt, lc) covers step lt, slot lc
    const int lc = tid & 15;
    const int lt = tid >> 4;

    float ru, rd, rg, rB, rC;

    #define LOAD_TILE(tile) do {                                              \
        int m = mb + (tile) * TQ + lt;                                        \
        ru = g_xc [(size_t)m * DI  + i_base + lc];                            \
        rd = g_dbc[(size_t)m * NC2 + i_base + lc];                            \
        if (PASS == 1) rg = g_gate[(size_t)m * DI + i_base + lc];             \
        rB = g_dbc[(size_t)m * NC2 + 1024 + lc];                              \
        rC = g_dbc[(size_t)m * NC2 + 1040 + lc];                              \
    } while (0)

    #define STS_TILE(buf) do {                                                \
        ud_s[buf][lt][lc] = make_float4(ru, rd, (PASS == 1) ? rg : 0.f, 0.f); \
        bc_s[buf][lt][lc] = make_float2(rB, rC);                              \
    } while (0)

    LOAD_TILE(0);
    STS_TILE(0);

    const int sidx0 = b * (DI * DS) + i * DS + s;
    float h = 0.f, ap;
    if (PASS == 0) {
        ap = 1.f;
    } else {
        for (int ch = 0; ch < chunk; ++ch) {
            int o = ch * CHST + sidx0;
            h = fmaf(g_ap[o], h, g_hl[o]);
        }
    }
    __syncthreads();

    const unsigned fm = 0xffffffffu;
    const int NT = CHL / TQ;                        // 8 tiles per chunk

    for (int tile = 0; tile < NT; ++tile) {
        const int cur = tile & 1, nxt = cur ^ 1;
        if (tile + 1 < NT) LOAD_TILE(tile + 1);

        #pragma unroll
        for (int tt = 0; tt < TQ; ++tt) {
            float4 ud = ud_s[cur][tt][c];
            float2 bc = bc_s[cur][tt][s];

            float a2 = fminf(fmaxf(ud.y * ALs2, -CLP2), CLP2);
            float dA = ex2f(a2);
            if (PASS == 0) ap *= dA;
            h = fmaf(dA, h, (ud.y * ud.x) * bc.x);

            if (PASS == 1) {
                float p = h * bc.y;
                p += __shfl_xor_sync(fm, p, 1);
                p += __shfl_xor_sync(fm, p, 2);
                p += __shfl_xor_sync(fm, p, 4);
                p += __shfl_xor_sync(fm, p, 8);

                if (s == 0) {
                    int m = mb + tile * TQ + tt;
                    float v = fmaf(ud.x, Dsk, p) * ud.z;
                    g_ygh[(size_t)m * DI + i] = __float2half_rn(v);
                }
            }
        }

        if (tile + 1 < NT) STS_TILE(nxt);
        __syncthreads();
    }

    if (PASS == 0) {
        int o = chunk * CHST + sidx0;
        g_hl[o] = h;
        g_ap[o] = ap;
    }
    #undef LOAD_TILE
    #undef STS_TILE
}

// ---------------------------------------------------------------------------
// residual + layernorm.  one warp per row (512 cols).
// ---------------------------------------------------------------------------
__global__ __launch_bounds__(256)
void ln_kernel(const float* __restrict__ x,
               const float* __restrict__ gamma,
               const float* __restrict__ beta,
               float* __restrict__ out)
{
    const int w = threadIdx.x >> 5;
    const int lane = threadIdx.x & 31;
    const int row = blockIdx.x * 8 + w;

    const float4* orow = (const float4*)&g_o[(size_t)row * DM];
    const float4* xrow = (const float4*)&x[(size_t)row * DM];

    float vals[16];
    float sum = 0.f, sq = 0.f;
    #pragma unroll
    for (int j = 0; j < 4; ++j) {
        float4 o = orow[lane + j * 32];
        float4 xv = xrow[lane + j * 32];
        float r0 = o.x + fminf(fmaxf(xv.x, -10.f), 10.f);
        float r1 = o.y + fminf(fmaxf(xv.y, -10.f), 10.f);
        float r2 = o.z + fminf(fmaxf(xv.z, -10.f), 10.f);
        float r3 = o.w + fminf(fmaxf(xv.w, -10.f), 10.f);
        vals[j * 4 + 0] = r0; vals[j * 4 + 1] = r1;
        vals[j * 4 + 2] = r2; vals[j * 4 + 3] = r3;
        sum += r0 + r1 + r2 + r3;
        sq  += r0 * r0 + r1 * r1 + r2 * r2 + r3 * r3;
    }
    #pragma unroll
    for (int off = 16; off >= 1; off >>= 1) {
        sum += __shfl_xor_sync(0xffffffffu, sum, off);
        sq  += __shfl_xor_sync(0xffffffffu, sq,  off);
    }
    const float mean = sum * (1.f / DM);
    const float var  = sq * (1.f / DM) - mean * mean;
    const float rstd = rsqrtf(var + 1e-5f);

    #pragma unroll
    for (int j = 0; j < 4; ++j) {
        float4 gm = ((const float4*)gamma)[lane + j * 32];
        float4 bt = ((const float4*)beta)[lane + j * 32];
        float4 o;
        o.x = fmaf((vals[j*4+0] - mean) * rstd, gm.x, bt.x);
        o.y = fmaf((vals[j*4+1] - mean) * rstd, gm.y, bt.y);
        o.z = fmaf((vals[j*4+2] - mean) * rstd, gm.z, bt.z);
        o.w = fmaf((vals[j*4+3] - mean) * rstd, gm.w, bt.w);
        ((float4*)&out[(size_t)row * DM])[lane + j * 32] = o;
    }
}

// ---------------------------------------------------------------------------
extern "C" void kernel_launch(void* const* d_in, const int* in_sizes, int n_in,
                              void* d_out, int out_size)
{
    const float* x      = (const float*)d_in[0];
    const float* W_in   = (const float*)d_in[1];
    const float* conv_w = (const float*)d_in[2];
    const float* conv_b = (const float*)d_in[3];
    const float* W_x    = (const float*)d_in[4];
    const float* W_dt   = (const float*)d_in[5];
    const float* b_dt   = (const float*)d_in[6];
    const float* A_log  = (const float*)d_in[7];
    const float* D_skip = (const float*)d_in[8];
    const float* W_out  = (const float*)d_in[9];
    const float* gamma  = (const float*)d_in[10];
    const float* beta   = (const float*)d_in[11];
    float* out = (float*)d_out;

    cudaFuncSetAttribute(mmagemm_kernel<false>,
                         cudaFuncAttributeMaxDynamicSharedMemorySize, GEMM_SMEM);
    cudaFuncSetAttribute(mmagemm_kernel<true>,
                         cudaFuncAttributeMaxDynamicSharedMemorySize, GEMM_SMEM);

    void *p_xr, *p_dbc, *p_o, *p_bc;
    void *p_xh, *p_xch, *p_ygh, *p_w1h, *p_w3h, *p_w4h;
    cudaGetSymbolAddress(&p_xr,  g_xr);
    cudaGetSymbolAddress(&p_dbc, g_dbc);
    cudaGetSymbolAddress(&p_o,   g_o);
    cudaGetSymbolAddress(&p_bc,  g_bc);
    cudaGetSymbolAddress(&p_xh,  g_xh);
    cudaGetSymbolAddress(&p_xch, g_xch);
    cudaGetSymbolAddress(&p_ygh, g_ygh);
    cudaGetSymbolAddress(&p_w1h, g_w1h);
    cudaGetSymbolAddress(&p_w3h, g_w3h);
    cudaGetSymbolAddress(&p_w4h, g_w4h);

    // fused operand prep (clip+cvt x, transpose+cvt weights, zpad, bias)
    prep_kernel<<<PREP_BLOCKS, 256>>>(x, W_in, W_dt, W_x, W_out, b_dt);

    // G1: xr = clip(x) @ W_in   [4096 x 2048], K=512
    {
        dim3 grid(2048 / 128, M_ROWS / 128);
        mmagemm_kernel<false><<<grid, 256, GEMM_SMEM>>>(
            (const h16*)p_xh, (const h16*)p_w1h,
            nullptr, (float*)p_xr, DM, 2048);
    }

    // conv + silu -> xc (fp32 + fp16), gate
    conv_silu_kernel<<<(M_ROWS * DI) / 256, 256>>>(conv_w, conv_b);

    // G3: dbc = xc @ Wcomb + bcomb   [4096 x 1152], K=1024
    {
        dim3 grid(NC2 / 128, M_ROWS / 128);
        mmagemm_kernel<true><<<grid, 256, GEMM_SMEM>>>(
            (const h16*)p_xch, (const h16*)p_w3h,
            (const float*)p_bc, (float*)p_dbc, DI, NC2);
    }

    // chunked selective scan: pass 0 (local, 7/8 chunks), pass 1 (combine + emit)
    scan_pass_kernel<0><<<NB * 64 * NCH, 256>>>(A_log, D_skip);
    scan_pass_kernel<1><<<NB * 64 * NCH, 256>>>(A_log, D_skip);

    // G4: o = yg @ W_out   [4096 x 512], K=1024
    {
        dim3 grid(DM / 128, M_ROWS / 128);
        mmagemm_kernel<false><<<grid, 256, GEMM_SMEM>>>(
            (const h16*)p_ygh, (const h16*)p_w4h,
            nullptr, (float*)p_o, DI, DM);
    }

    // residual + layernorm -> out
    ln_kernel<<<M_ROWS / 8, 256>>>(x, gamma, beta, out);
}